// round 8
// baseline (speedup 1.0000x reference)
#include <cuda_runtime.h>
#include <math.h>
#include <stdint.h>

#define BATCH  16
#define CDIM   256
#define NPIX   4096
#define NHEADS 4
#define DHEAD  32
#define HID    128
#define CHW    128
#define NGRP   8             // chunk-groups per (b,h); 4 chunks of 128 each
#define APITCH 12            // As pitch (u32): frag bank = (12g+t)%32, all 32 distinct
#define BPITCH 136           // Bs pitch: 136%32==8 -> frag bank = 8(t+nt)+g, distinct
#define CPITCH 132           // ctx smem pitch
#define NST    4             // cp.async pipeline stages
#define ASZ    (256 * APITCH)          // 3072 u32 per stage
#define BSZ    (8 * BPITCH)            // 1088 u32 per stage
#define STAGE_U32 (ASZ + BSZ)          // 4160
#define GEMM_SMEM (NST * STAGE_U32 * 4)  // 66560 bytes

// Scratch (device globals: allocation-free per harness rules)
__device__ float  g_qkv [BATCH * 256 * NPIX];        // rows 0-127 = q (raw, then normexp'd in place), 128-255 = v
__device__ float  g_ctxp[BATCH * NHEADS * NGRP * DHEAD * DHEAD];  // 2 MB partials
__device__ float  g_W2  [BATCH * CDIM * HID];
__device__ float2 g_stats[BATCH * HID];              // per q-row {max, 1/sumexp}

__device__ __forceinline__ uint32_t f2tf32(float f)
{
    uint32_t u;
    asm("cvt.rna.tf32.f32 %0, %1;" : "=r"(u) : "f"(f));
    return u;
}

__device__ __forceinline__ void mma_tf32(float c[4],
    uint32_t a0, uint32_t a1, uint32_t a2, uint32_t a3,
    uint32_t b0, uint32_t b1)
{
    asm volatile(
        "mma.sync.aligned.m16n8k8.row.col.f32.tf32.tf32.f32 "
        "{%0,%1,%2,%3}, {%4,%5,%6,%7}, {%8,%9}, {%0,%1,%2,%3};"
        : "+f"(c[0]), "+f"(c[1]), "+f"(c[2]), "+f"(c[3])
        : "r"(a0), "r"(a1), "r"(a2), "r"(a3), "r"(b0), "r"(b1));
}

__device__ __forceinline__ float4 normexp4(float4 v, float2 st)
{
    float4 r;
    r.x = __expf(v.x - st.x) * st.y;
    r.y = __expf(v.y - st.x) * st.y;
    r.z = __expf(v.z - st.x) * st.y;
    r.w = __expf(v.w - st.x) * st.y;
    return r;
}

#define CP_ASYNC16(dst, src) \
    asm volatile("cp.async.ca.shared.global [%0], [%1], 16;" :: "r"(dst), "l"(src))
#define CP_COMMIT() asm volatile("cp.async.commit_group;")
#define CP_WAIT2()  asm volatile("cp.async.wait_group 2;")

// ---------------------------------------------------------------------------
// tf32 tensor-core GEMM, 4-stage cp.async pipeline.
// C[b](256 x 4096) = A[b](256 x K row-major, rows >=128 offset by aSkip) * B[b](K x 4096)
// Block tile 256x128, BK=8, 256 threads = 8 warps (4m x 2n), warp tile 64x64.
// tf32 conversion (cvt.rna) applied at fragment-load time.
// ---------------------------------------------------------------------------
__global__ void __launch_bounds__(256)
gemm_tf32(const float* __restrict__ A, const float* __restrict__ B,
          float* __restrict__ C, int K,
          size_t sA, size_t sB, size_t sC, int aSkip)
{
    extern __shared__ uint32_t sm[];

    int b  = blockIdx.z;
    int bx = blockIdx.x;
    const float* Ab = A + (size_t)b * sA;
    const float* Bb = B + (size_t)b * sB + bx * 128;
    float*       Cb = C + (size_t)b * sC + bx * 128;

    int tid  = threadIdx.x;
    int lane = tid & 31, warp = tid >> 5;
    int g = lane >> 2, t = lane & 3;
    int wm = (warp >> 1) * 64;          // warp m-base: 0,64,128,192
    int wn = (warp & 1) * 64;           // warp n-base: 0,64

    // loaders
    int arow = tid;                                   // 0..255
    int grow = arow + (arow >= 128 ? aSkip : 0);
    const float* ag = Ab + (size_t)grow * K;
    int bk  = tid >> 5;                               // 0..7
    int bn4 = (lane) * 4;                             // 0..124
    const float* bg = Bb + (size_t)bk * NPIX + bn4;

    uint32_t smem_base = (uint32_t)__cvta_generic_to_shared(sm);
    int nsteps = K >> 3;

    // issue stage s
    auto issue = [&](int s) {
        if (s < nsteps) {
            uint32_t st = (uint32_t)(s & (NST - 1)) * (STAGE_U32 * 4);
            uint32_t da = smem_base + st + (uint32_t)arow * (APITCH * 4);
            const float* ap = ag + s * 8;
            CP_ASYNC16(da,      ap);
            CP_ASYNC16(da + 16, ap + 4);
            uint32_t db = smem_base + st + ASZ * 4 + ((uint32_t)bk * BPITCH + bn4) * 4;
            CP_ASYNC16(db, bg + (size_t)s * 8 * NPIX);
        }
        CP_COMMIT();
    };

    issue(0); issue(1); issue(2);

    float acc[4][8][4] = {};            // [mt][nt][frag]

    for (int s = 0; s < nsteps; s++) {
        CP_WAIT2();
        __syncthreads();
        issue(s + 3);

        const uint32_t* As = sm + (s & (NST - 1)) * STAGE_U32;
        const uint32_t* Bs = As + ASZ;

        uint32_t af[4][4], bf[8][2];
#pragma unroll
        for (int mt = 0; mt < 4; mt++) {
            int r = wm + mt * 16 + g;
            af[mt][0] = f2tf32(__uint_as_float(As[r * APITCH + t]));
            af[mt][1] = f2tf32(__uint_as_float(As[(r + 8) * APITCH + t]));
            af[mt][2] = f2tf32(__uint_as_float(As[r * APITCH + t + 4]));
            af[mt][3] = f2tf32(__uint_as_float(As[(r + 8) * APITCH + t + 4]));
        }
#pragma unroll
        for (int nt = 0; nt < 8; nt++) {
            int c = wn + nt * 8 + g;
            bf[nt][0] = f2tf32(__uint_as_float(Bs[t * BPITCH + c]));
            bf[nt][1] = f2tf32(__uint_as_float(Bs[(t + 4) * BPITCH + c]));
        }
#pragma unroll
        for (int mt = 0; mt < 4; mt++)
#pragma unroll
            for (int nt = 0; nt < 8; nt++)
                mma_tf32(acc[mt][nt],
                         af[mt][0], af[mt][1], af[mt][2], af[mt][3],
                         bf[nt][0], bf[nt][1]);
    }

#pragma unroll
    for (int mt = 0; mt < 4; mt++) {
        int r0 = wm + mt * 16 + g;
#pragma unroll
        for (int nt = 0; nt < 8; nt++) {
            int c0 = wn + nt * 8 + 2 * t;
            float2 lo = {acc[mt][nt][0], acc[mt][nt][1]};
            float2 hi = {acc[mt][nt][2], acc[mt][nt][3]};
            *(float2*)&Cb[(size_t)r0       * NPIX + c0] = lo;
            *(float2*)&Cb[(size_t)(r0 + 8) * NPIX + c0] = hi;
        }
    }
}

// ---------------------------------------------------------------------------
// Row stats for softmax over n: per q-row {max, 1/sum(exp(x-max))}.
// ---------------------------------------------------------------------------
__global__ void stats_kernel()
{
    int r = blockIdx.x;                 // 0..2047
    int b = r >> 7, q = r & 127;
    const float* row = g_qkv + (size_t)b * 256 * NPIX + (size_t)q * NPIX;
    int tid = threadIdx.x;

    float v[16];
    float m = -1e30f;
#pragma unroll
    for (int i = 0; i < 16; i++) { v[i] = row[tid + i * 256]; m = fmaxf(m, v[i]); }

    __shared__ float red[8];
#pragma unroll
    for (int o = 16; o > 0; o >>= 1) m = fmaxf(m, __shfl_xor_sync(~0u, m, o));
    if ((tid & 31) == 0) red[tid >> 5] = m;
    __syncthreads();
    m = red[0];
#pragma unroll
    for (int i = 1; i < 8; i++) m = fmaxf(m, red[i]);
    __syncthreads();

    float s = 0.f;
#pragma unroll
    for (int i = 0; i < 16; i++) s += __expf(v[i] - m);
#pragma unroll
    for (int o = 16; o > 0; o >>= 1) s += __shfl_xor_sync(~0u, s, o);
    if ((tid & 31) == 0) red[tid >> 5] = s;
    __syncthreads();
    if (tid == 0) {
        s = red[0];
#pragma unroll
        for (int i = 1; i < 8; i++) s += red[i];
        g_stats[r] = make_float2(m, 1.0f / s);
    }
}

// ---------------------------------------------------------------------------
// Fused: softmax-n applied on load (and written back in place so gemm2 reads
// normalized q) + per-column softmax over d + partial context via tf32 MMA.
// One block per (b, h, chunk-group); each block accumulates 4 n-chunks of 128.
// ---------------------------------------------------------------------------
__global__ void __launch_bounds__(256) ctx_part_kernel()
{
    int bid = blockIdx.x;               // 0..511
    int p   = bid & (NGRP - 1);
    int bh  = bid >> 3;
    int b   = bh >> 2, h = bh & 3;

    float* qp_base = g_qkv + ((size_t)b * 256 + h * DHEAD) * NPIX;
    const float* vp_base = g_qkv + ((size_t)b * 256 + 128 + h * DHEAD) * NPIX;

    __shared__ float kst[DHEAD][CPITCH];
    __shared__ float vst[DHEAD][CPITCH];

    int tid = threadIdx.x;
    int lane = tid & 31, warp = tid >> 5;
    int g = lane >> 2, t = lane & 3;
    int mrow = (warp >> 2) * 16;
    int ncol = (warp & 3) * 8;

    float acc[4] = {};

    for (int c4 = 0; c4 < 4; c4++) {
        int n0 = (p * 4 + c4) * CHW;
        if (c4) __syncthreads();        // smem reuse guard

#pragma unroll
        for (int r = 0; r < 4; r++) {
            int idx = tid + r * 256;
            int row = idx >> 5;         // d 0..31
            int col = (idx & 31) * 4;
            float2 st = g_stats[(b << 7) + (h << 5) + row];
            float4 qv = *(const float4*)&qp_base[(size_t)row * NPIX + n0 + col];
            float4 nq = normexp4(qv, st);
            *(float4*)&kst[row][col] = nq;
            *(float4*)&qp_base[(size_t)row * NPIX + n0 + col] = nq;  // write back for gemm2
            *(float4*)&vst[row][col] = *(const float4*)&vp_base[(size_t)row * NPIX + n0 + col];
        }
        __syncthreads();

        // per-column softmax over d
        if (tid < CHW) {
            float e[DHEAD];
            float m = -1e30f;
#pragma unroll
            for (int d = 0; d < DHEAD; d++) { e[d] = kst[d][tid]; m = fmaxf(m, e[d]); }
            float s = 0.f;
#pragma unroll
            for (int d = 0; d < DHEAD; d++) { e[d] = __expf(e[d] - m); s += e[d]; }
            float inv = 1.0f / s;
#pragma unroll
            for (int d = 0; d < DHEAD; d++) kst[d][tid] = e[d] * inv;
        }
        __syncthreads();

#pragma unroll
        for (int k8 = 0; k8 < CHW; k8 += 8) {
            uint32_t a0 = f2tf32(kst[mrow + g    ][k8 + t]);
            uint32_t a1 = f2tf32(kst[mrow + g + 8][k8 + t]);
            uint32_t a2 = f2tf32(kst[mrow + g    ][k8 + t + 4]);
            uint32_t a3 = f2tf32(kst[mrow + g + 8][k8 + t + 4]);
            uint32_t b0 = f2tf32(vst[ncol + g][k8 + t]);
            uint32_t b1 = f2tf32(vst[ncol + g][k8 + t + 4]);
            mma_tf32(acc, a0, a1, a2, a3, b0, b1);
        }
    }

    float* pp = g_ctxp + ((size_t)bh * NGRP + p) * 1024;
    float2 lo = {acc[0], acc[1]};
    float2 hi = {acc[2], acc[3]};
    *(float2*)&pp[(mrow + g    ) * DHEAD + ncol + 2 * t] = lo;
    *(float2*)&pp[(mrow + g + 8) * DHEAD + ncol + 2 * t] = hi;
}

// ---------------------------------------------------------------------------
// Merged: reduce ctx partials (fixed order) + compose W2 = w_out o ctx.
// ---------------------------------------------------------------------------
__global__ void __launch_bounds__(256) ctxw2_kernel(const float* __restrict__ w_out)
{
    int bh = blockIdx.x;                // b*4 + h
    int b  = bh >> 2, h = bh & 3;

    __shared__ float ctx[1024];         // [k][v] 32x32
    int tid = threadIdx.x;
    const float* base = g_ctxp + (size_t)bh * (NGRP * 1024);

#pragma unroll
    for (int j = 0; j < 4; j++) {
        int e = tid + j * 256;
        float s = 0.f;
#pragma unroll
        for (int p = 0; p < NGRP; p++) s += base[p * 1024 + e];
        ctx[e] = s;
    }
    __syncthreads();

    int o = tid;
    float wrow[32];
#pragma unroll
    for (int v = 0; v < 32; v++) wrow[v] = w_out[o * HID + h * DHEAD + v];

    float* w2p = g_W2 + ((size_t)b * CDIM + o) * HID + h * DHEAD;
#pragma unroll
    for (int kk = 0; kk < 32; kk++) {
        float s = 0.f;
#pragma unroll
        for (int v = 0; v < 32; v++) s = fmaf(wrow[v], ctx[kk * 32 + v], s);
        w2p[kk] = s;
    }
}

// ---------------------------------------------------------------------------
extern "C" void kernel_launch(void* const* d_in, const int* in_sizes, int n_in,
                              void* d_out, int out_size)
{
    const float* x     = (const float*)d_in[0];
    const float* w_qkv = (const float*)d_in[1];
    const float* w_out = (const float*)d_in[2];
    float*       out   = (float*)d_out;

    float *qkv_p, *w2_p;
    cudaGetSymbolAddress((void**)&qkv_p, g_qkv);
    cudaGetSymbolAddress((void**)&w2_p,  g_W2);

    cudaFuncSetAttribute(gemm_tf32, cudaFuncAttributeMaxDynamicSharedMemorySize, GEMM_SMEM);

    dim3 gg(NPIX / 128, 1, BATCH);      // 512 blocks, M=256 per block

    // 1) q and v projections: A rows 0-127 -> w_qkv q rows, 128-255 -> w_qkv v rows (skip k_proj)
    gemm_tf32<<<gg, 256, GEMM_SMEM>>>(w_qkv, x, qkv_p, CDIM,
                                      0, (size_t)CDIM * NPIX, (size_t)256 * NPIX, 128);
    // 2) per-row softmax-n stats
    stats_kernel<<<BATCH * HID, 256>>>();
    // 3) fused softmax-n (applied + written back) + softmax-d + partial ctx
    ctx_part_kernel<<<BATCH * NHEADS * NGRP, 256>>>();
    // 4) merged reduce + W2 compose
    ctxw2_kernel<<<BATCH * NHEADS, 256>>>(w_out);
    // 5) y = W2 @ normalized q
    gemm_tf32<<<gg, 256, GEMM_SMEM>>>(w2_p, qkv_p, out, HID,
                                      (size_t)CDIM * HID, (size_t)256 * NPIX,
                                      (size_t)CDIM * NPIX, 0);
}

// round 13
// speedup vs baseline: 1.2712x; 1.2712x over previous
#include <cuda_runtime.h>
#include <math.h>
#include <stdint.h>

#define BATCH  16
#define CDIM   256
#define NPIX   4096
#define NHEADS 4
#define DHEAD  32
#define HID    128
#define CHW    128
#define NGRP   8             // chunk-groups per (b,h); 4 chunks of 128 each
#define PAD    20            // As pitch: frag bank = (20g+t)%32, all 32 distinct
#define BPITCH 136           // Bs pitch: 136%32==8 -> frag bank = 8t+g, all 32 distinct
#define CPITCH 132           // ctx smem pitch

// Scratch (device globals: allocation-free per harness rules)
__device__ float  g_qkv [BATCH * 256 * NPIX];        // rows 0-127 = raw q, 128-255 = v
__device__ float  g_ctxp[BATCH * NHEADS * NGRP * DHEAD * DHEAD];  // 2 MB partials
__device__ float  g_W2  [BATCH * CDIM * HID];
__device__ float2 g_stats[BATCH * HID];              // per q-row {max, 1/sumexp}

__device__ __forceinline__ uint32_t f2tf32(float f)
{
    uint32_t u;
    asm("cvt.rna.tf32.f32 %0, %1;" : "=r"(u) : "f"(f));
    return u;
}

__device__ __forceinline__ void mma_tf32(float c[4],
    uint32_t a0, uint32_t a1, uint32_t a2, uint32_t a3,
    uint32_t b0, uint32_t b1)
{
    asm volatile(
        "mma.sync.aligned.m16n8k8.row.col.f32.tf32.tf32.f32 "
        "{%0,%1,%2,%3}, {%4,%5,%6,%7}, {%8,%9}, {%0,%1,%2,%3};"
        : "+f"(c[0]), "+f"(c[1]), "+f"(c[2]), "+f"(c[3])
        : "r"(a0), "r"(a1), "r"(a2), "r"(a3), "r"(b0), "r"(b1));
}

__device__ __forceinline__ uint4 cvt4(float4 v)
{
    uint4 u;
    u.x = f2tf32(v.x); u.y = f2tf32(v.y); u.z = f2tf32(v.z); u.w = f2tf32(v.w);
    return u;
}

__device__ __forceinline__ float4 normexp4(float4 v, float2 st)
{
    float4 r;
    r.x = __expf(v.x - st.x) * st.y;
    r.y = __expf(v.y - st.x) * st.y;
    r.z = __expf(v.z - st.x) * st.y;
    r.w = __expf(v.w - st.x) * st.y;
    return r;
}

// ---------------------------------------------------------------------------
// tf32 tensor-core GEMM, double-buffered, conflict-free smem (round-7 proven).
// If stats != nullptr, B rows are transformed exp(x-m)*inv on the fly.
// Block tile 128x128, BK=16, 256 threads = 8 warps (4m x 2n), warp tile 32x64.
// ---------------------------------------------------------------------------
__global__ void __launch_bounds__(256)
gemm_tf32(const float* __restrict__ A, const float* __restrict__ B,
          float* __restrict__ C, int K,
          size_t sA, size_t sB, size_t sC, int aJump,
          const float2* __restrict__ stats)
{
    __shared__ uint32_t As[2][128][PAD];      // [buf][m][k]
    __shared__ uint32_t Bs[2][16][BPITCH];    // [buf][k][n]

    int b = blockIdx.z;
    const float* Ab = A + (size_t)b * sA + (size_t)(blockIdx.y * aJump) * K;
    const float* Bb = B + (size_t)b * sB + blockIdx.x * 128;
    float*       Cb = C + (size_t)b * sC + (size_t)(blockIdx.y * 128) * NPIX + blockIdx.x * 128;
    const float2* stb = stats ? stats + b * HID : nullptr;

    int tid  = threadIdx.x;
    int lane = tid & 31, warp = tid >> 5;
    int g = lane >> 2, t = lane & 3;
    int wm = (warp >> 1) * 32;
    int wn = (warp & 1) * 64;

    int arow = tid >> 1, akb = (tid & 1) * 8;     // A loader: 128 rows x 16 k
    int bk   = tid >> 4, bnb = (tid & 15) * 8;    // B loader: 16 k x 128 n

    const float* aPtr = &Ab[(size_t)arow * K + akb];
    const float* bPtr = &Bb[(size_t)bk * NPIX + bnb];

    float acc[2][8][4] = {};
    float4 ra0, ra1, rb0, rb1;

    // prologue: load + stage tile 0
    ra0 = *(const float4*)&aPtr[0];
    ra1 = *(const float4*)&aPtr[4];
    rb0 = *(const float4*)&bPtr[0];
    rb1 = *(const float4*)&bPtr[4];
    if (stb) {
        float2 st = stb[bk];
        rb0 = normexp4(rb0, st);
        rb1 = normexp4(rb1, st);
    }
    *(uint4*)&As[0][arow][akb]     = cvt4(ra0);
    *(uint4*)&As[0][arow][akb + 4] = cvt4(ra1);
    *(uint4*)&Bs[0][bk][bnb]       = cvt4(rb0);
    *(uint4*)&Bs[0][bk][bnb + 4]   = cvt4(rb1);
    __syncthreads();

    int nsteps = K >> 4;
    for (int s = 0; s < nsteps; s++) {
        int cur = s & 1;
        int has_next = (s + 1 < nsteps);

        if (has_next) {
            const float* ap = aPtr + (s + 1) * 16;
            const float* bp = bPtr + (size_t)(s + 1) * 16 * NPIX;
            ra0 = *(const float4*)&ap[0];
            ra1 = *(const float4*)&ap[4];
            rb0 = *(const float4*)&bp[0];
            rb1 = *(const float4*)&bp[4];
            if (stb) {
                float2 st = stb[(s + 1) * 16 + bk];
                rb0 = normexp4(rb0, st);
                rb1 = normexp4(rb1, st);
            }
        }

#pragma unroll
        for (int k8 = 0; k8 < 16; k8 += 8) {
            uint32_t af[2][4], bf[8][2];
#pragma unroll
            for (int mt = 0; mt < 2; mt++) {
                int r = wm + mt * 16 + g;
                af[mt][0] = As[cur][r    ][k8 + t];
                af[mt][1] = As[cur][r + 8][k8 + t];
                af[mt][2] = As[cur][r    ][k8 + t + 4];
                af[mt][3] = As[cur][r + 8][k8 + t + 4];
            }
#pragma unroll
            for (int nt = 0; nt < 8; nt++) {
                int c = wn + nt * 8 + g;
                bf[nt][0] = Bs[cur][k8 + t    ][c];
                bf[nt][1] = Bs[cur][k8 + t + 4][c];
            }
#pragma unroll
            for (int mt = 0; mt < 2; mt++)
#pragma unroll
                for (int nt = 0; nt < 8; nt++)
                    mma_tf32(acc[mt][nt],
                             af[mt][0], af[mt][1], af[mt][2], af[mt][3],
                             bf[nt][0], bf[nt][1]);
        }

        if (has_next) {
            int nxt = cur ^ 1;
            *(uint4*)&As[nxt][arow][akb]     = cvt4(ra0);
            *(uint4*)&As[nxt][arow][akb + 4] = cvt4(ra1);
            *(uint4*)&Bs[nxt][bk][bnb]       = cvt4(rb0);
            *(uint4*)&Bs[nxt][bk][bnb + 4]   = cvt4(rb1);
            __syncthreads();
        }
    }

#pragma unroll
    for (int mt = 0; mt < 2; mt++) {
        int r0 = wm + mt * 16 + g;
#pragma unroll
        for (int nt = 0; nt < 8; nt++) {
            int c0 = wn + nt * 8 + 2 * t;
            float2 lo = {acc[mt][nt][0], acc[mt][nt][1]};
            float2 hi = {acc[mt][nt][2], acc[mt][nt][3]};
            *(float2*)&Cb[(size_t)r0       * NPIX + c0] = lo;
            *(float2*)&Cb[(size_t)(r0 + 8) * NPIX + c0] = hi;
        }
    }
}

// ---------------------------------------------------------------------------
// Row stats for softmax over n: per q-row {max, 1/sum(exp(x-max))}.
// ---------------------------------------------------------------------------
__global__ void stats_kernel()
{
    int r = blockIdx.x;                 // 0..2047
    int b = r >> 7, q = r & 127;
    const float* row = g_qkv + (size_t)b * 256 * NPIX + (size_t)q * NPIX;
    int tid = threadIdx.x;

    float v[16];
    float m = -1e30f;
#pragma unroll
    for (int i = 0; i < 16; i++) { v[i] = row[tid + i * 256]; m = fmaxf(m, v[i]); }

    __shared__ float red[8];
#pragma unroll
    for (int o = 16; o > 0; o >>= 1) m = fmaxf(m, __shfl_xor_sync(~0u, m, o));
    if ((tid & 31) == 0) red[tid >> 5] = m;
    __syncthreads();
    m = red[0];
#pragma unroll
    for (int i = 1; i < 8; i++) m = fmaxf(m, red[i]);
    __syncthreads();

    float s = 0.f;
#pragma unroll
    for (int i = 0; i < 16; i++) s += __expf(v[i] - m);
#pragma unroll
    for (int o = 16; o > 0; o >>= 1) s += __shfl_xor_sync(~0u, s, o);
    if ((tid & 31) == 0) red[tid >> 5] = s;
    __syncthreads();
    if (tid == 0) {
        s = red[0];
#pragma unroll
        for (int i = 1; i < 8; i++) s += red[i];
        g_stats[r] = make_float2(m, 1.0f / s);
    }
}

// ---------------------------------------------------------------------------
// Fused: softmax-n applied on load + per-column softmax over d + partial
// context via tf32 MMA. One block per (b, h, chunk-group of 4x128 n).
// ---------------------------------------------------------------------------
__global__ void __launch_bounds__(256) ctx_part_kernel()
{
    int bid = blockIdx.x;               // 0..511
    int p   = bid & (NGRP - 1);
    int bh  = bid >> 3;
    int b   = bh >> 2, h = bh & 3;

    const float* qp_base = g_qkv + ((size_t)b * 256 + h * DHEAD) * NPIX;
    const float* vp_base = g_qkv + ((size_t)b * 256 + 128 + h * DHEAD) * NPIX;

    __shared__ float kst[DHEAD][CPITCH];
    __shared__ float vst[DHEAD][CPITCH];

    int tid = threadIdx.x;
    int lane = tid & 31, warp = tid >> 5;
    int g = lane >> 2, t = lane & 3;
    int mrow = (warp >> 2) * 16;
    int ncol = (warp & 3) * 8;

    float acc[4] = {};

    for (int c4 = 0; c4 < 4; c4++) {
        int n0 = (p * 4 + c4) * CHW;
        if (c4) __syncthreads();        // smem reuse guard

#pragma unroll
        for (int r = 0; r < 4; r++) {
            int idx = tid + r * 256;
            int row = idx >> 5;         // d 0..31
            int col = (idx & 31) * 4;
            float2 st = g_stats[(b << 7) + (h << 5) + row];
            float4 qv = *(const float4*)&qp_base[(size_t)row * NPIX + n0 + col];
            *(float4*)&kst[row][col] = normexp4(qv, st);   // softmax-n applied
            *(float4*)&vst[row][col] = *(const float4*)&vp_base[(size_t)row * NPIX + n0 + col];
        }
        __syncthreads();

        // per-column softmax over d
        if (tid < CHW) {
            float e[DHEAD];
            float m = -1e30f;
#pragma unroll
            for (int d = 0; d < DHEAD; d++) { e[d] = kst[d][tid]; m = fmaxf(m, e[d]); }
            float s = 0.f;
#pragma unroll
            for (int d = 0; d < DHEAD; d++) { e[d] = __expf(e[d] - m); s += e[d]; }
            float inv = 1.0f / s;
#pragma unroll
            for (int d = 0; d < DHEAD; d++) kst[d][tid] = e[d] * inv;
        }
        __syncthreads();

#pragma unroll
        for (int k8 = 0; k8 < CHW; k8 += 8) {
            uint32_t a0 = f2tf32(kst[mrow + g    ][k8 + t]);
            uint32_t a1 = f2tf32(kst[mrow + g + 8][k8 + t]);
            uint32_t a2 = f2tf32(kst[mrow + g    ][k8 + t + 4]);
            uint32_t a3 = f2tf32(kst[mrow + g + 8][k8 + t + 4]);
            uint32_t b0 = f2tf32(vst[ncol + g][k8 + t]);
            uint32_t b1 = f2tf32(vst[ncol + g][k8 + t + 4]);
            mma_tf32(acc, a0, a1, a2, a3, b0, b1);
        }
    }

    float* pp = g_ctxp + ((size_t)bh * NGRP + p) * 1024;
    float2 lo = {acc[0], acc[1]};
    float2 hi = {acc[2], acc[3]};
    *(float2*)&pp[(mrow + g    ) * DHEAD + ncol + 2 * t] = lo;
    *(float2*)&pp[(mrow + g + 8) * DHEAD + ncol + 2 * t] = hi;
}

// ---------------------------------------------------------------------------
// Merged: reduce ctx partials (fixed order, 8 groups) + compose W2.
// ---------------------------------------------------------------------------
__global__ void __launch_bounds__(256) ctxw2_kernel(const float* __restrict__ w_out)
{
    int bh = blockIdx.x;                // b*4 + h
    int b  = bh >> 2, h = bh & 3;

    __shared__ float ctx[1024];         // [k][v] 32x32
    int tid = threadIdx.x;
    const float* base = g_ctxp + (size_t)bh * (NGRP * 1024);

#pragma unroll
    for (int j = 0; j < 4; j++) {
        int e = tid + j * 256;
        float s = 0.f;
#pragma unroll
        for (int p = 0; p < NGRP; p++) s += base[p * 1024 + e];
        ctx[e] = s;
    }
    __syncthreads();

    int o = tid;
    float wrow[32];
#pragma unroll
    for (int v = 0; v < 32; v++) wrow[v] = w_out[o * HID + h * DHEAD + v];

    float* w2p = g_W2 + ((size_t)b * CDIM + o) * HID + h * DHEAD;
#pragma unroll
    for (int kk = 0; kk < 32; kk++) {
        float s = 0.f;
#pragma unroll
        for (int v = 0; v < 32; v++) s = fmaf(wrow[v], ctx[kk * 32 + v], s);
        w2p[kk] = s;
    }
}

// ---------------------------------------------------------------------------
extern "C" void kernel_launch(void* const* d_in, const int* in_sizes, int n_in,
                              void* d_out, int out_size)
{
    const float* x     = (const float*)d_in[0];
    const float* w_qkv = (const float*)d_in[1];
    const float* w_out = (const float*)d_in[2];
    float*       out   = (float*)d_out;

    float  *qkv_p, *w2_p;
    float2 *st_p;
    cudaGetSymbolAddress((void**)&qkv_p, g_qkv);
    cudaGetSymbolAddress((void**)&w2_p,  g_W2);
    cudaGetSymbolAddress((void**)&st_p,  g_stats);

    dim3 gg(NPIX / 128, 2, BATCH);

    // 1) q and v projections (raw q stored)
    gemm_tf32<<<gg, 256>>>(w_qkv, x, qkv_p, CDIM,
                           0, (size_t)CDIM * NPIX, (size_t)256 * NPIX, 256, nullptr);
    // 2) per-row softmax-n stats
    stats_kernel<<<BATCH * HID, 256>>>();
    // 3) fused softmax-n(load) + softmax-d + partial ctx (tf32 MMA, 8 groups)
    ctx_part_kernel<<<BATCH * NHEADS * NGRP, 256>>>();
    // 4) merged reduce + W2 compose
    ctxw2_kernel<<<BATCH * NHEADS, 256>>>(w_out);
    // 5) y = W2 @ softmax_n(q), normalization applied in B-loader
    gemm_tf32<<<gg, 256>>>(w2_p, qkv_p, out, HID,
                           (size_t)CDIM * HID, (size_t)256 * NPIX, (size_t)CDIM * NPIX, 128,
                           st_p);
}

// round 14
// speedup vs baseline: 1.3663x; 1.0749x over previous
#include <cuda_runtime.h>
#include <math.h>
#include <stdint.h>

#define BATCH  16
#define CDIM   256
#define NPIX   4096
#define NHEADS 4
#define DHEAD  32
#define HID    128
#define CHW    128
#define NGRP   8             // chunk-groups per (b,h); 4 chunks of 128 each
#define PAD    20            // As pitch: frag bank = (20g+t)%32, all 32 distinct
#define BPITCH 136           // Bs pitch: 136%32==8 -> frag bank = 8t+g, all 32 distinct
#define CPITCH 132           // ctx smem pitch

// gemm2 cp.async pipeline geometry
#define G2_NST 3
#define G2_ASZ (128 * PAD)               // 2560 u32 per stage
#define G2_BSZ (16 * BPITCH)             // 2176 u32 per stage
#define G2_STG (G2_ASZ + G2_BSZ)         // 4736 u32
#define G2_SMEM (G2_NST * G2_STG * 4)    // 56832 bytes

// Scratch (device globals: allocation-free per harness rules)
__device__ float  g_qkv [BATCH * 256 * NPIX];        // rows 0-127 = q, 128-255 = v
__device__ float  g_ctxp[BATCH * NHEADS * NGRP * DHEAD * DHEAD];  // 2 MB partials
__device__ float  g_W2  [BATCH * CDIM * HID];        // stored tf32-rounded
__device__ float2 g_stats[BATCH * HID];              // per q-row {max, 1/sumexp}

__device__ __forceinline__ uint32_t f2tf32(float f)
{
    uint32_t u;
    asm("cvt.rna.tf32.f32 %0, %1;" : "=r"(u) : "f"(f));
    return u;
}

__device__ __forceinline__ void mma_tf32(float c[4],
    uint32_t a0, uint32_t a1, uint32_t a2, uint32_t a3,
    uint32_t b0, uint32_t b1)
{
    asm volatile(
        "mma.sync.aligned.m16n8k8.row.col.f32.tf32.tf32.f32 "
        "{%0,%1,%2,%3}, {%4,%5,%6,%7}, {%8,%9}, {%0,%1,%2,%3};"
        : "+f"(c[0]), "+f"(c[1]), "+f"(c[2]), "+f"(c[3])
        : "r"(a0), "r"(a1), "r"(a2), "r"(a3), "r"(b0), "r"(b1));
}

__device__ __forceinline__ uint4 cvt4(float4 v)
{
    uint4 u;
    u.x = f2tf32(v.x); u.y = f2tf32(v.y); u.z = f2tf32(v.z); u.w = f2tf32(v.w);
    return u;
}

__device__ __forceinline__ float4 normexp4(float4 v, float2 st)
{
    float4 r;
    r.x = __expf(v.x - st.x) * st.y;
    r.y = __expf(v.y - st.x) * st.y;
    r.z = __expf(v.z - st.x) * st.y;
    r.w = __expf(v.w - st.x) * st.y;
    return r;
}

#define CP_ASYNC16(dst, src) \
    asm volatile("cp.async.ca.shared.global [%0], [%1], 16;" :: "r"(dst), "l"(src))
#define CP_COMMIT() asm volatile("cp.async.commit_group;")
#define CP_WAIT1()  asm volatile("cp.async.wait_group 1;")

// ---------------------------------------------------------------------------
// gemm1: tf32 tensor-core GEMM, register-staged double buffer (proven R7).
// C[b](rows via aJump) = A[b](M x K row-major) * B[b](K x 4096).
// Block tile 128x128, BK=16, 8 warps (4m x 2n), warp tile 32x64.
// ---------------------------------------------------------------------------
__global__ void __launch_bounds__(256)
gemm_tf32(const float* __restrict__ A, const float* __restrict__ B,
          float* __restrict__ C, int K,
          size_t sA, size_t sB, size_t sC, int aJump)
{
    __shared__ uint32_t As[2][128][PAD];      // [buf][m][k]
    __shared__ uint32_t Bs[2][16][BPITCH];    // [buf][k][n]

    int b = blockIdx.z;
    const float* Ab = A + (size_t)b * sA + (size_t)(blockIdx.y * aJump) * K;
    const float* Bb = B + (size_t)b * sB + blockIdx.x * 128;
    float*       Cb = C + (size_t)b * sC + (size_t)(blockIdx.y * 128) * NPIX + blockIdx.x * 128;

    int tid  = threadIdx.x;
    int lane = tid & 31, warp = tid >> 5;
    int g = lane >> 2, t = lane & 3;
    int wm = (warp >> 1) * 32;
    int wn = (warp & 1) * 64;

    int arow = tid >> 1, akb = (tid & 1) * 8;     // A loader: 128 rows x 16 k
    int bk   = tid >> 4, bnb = (tid & 15) * 8;    // B loader: 16 k x 128 n

    const float* aPtr = &Ab[(size_t)arow * K + akb];
    const float* bPtr = &Bb[(size_t)bk * NPIX + bnb];

    float acc[2][8][4] = {};
    float4 ra0, ra1, rb0, rb1;

    ra0 = *(const float4*)&aPtr[0];
    ra1 = *(const float4*)&aPtr[4];
    rb0 = *(const float4*)&bPtr[0];
    rb1 = *(const float4*)&bPtr[4];
    *(uint4*)&As[0][arow][akb]     = cvt4(ra0);
    *(uint4*)&As[0][arow][akb + 4] = cvt4(ra1);
    *(uint4*)&Bs[0][bk][bnb]       = cvt4(rb0);
    *(uint4*)&Bs[0][bk][bnb + 4]   = cvt4(rb1);
    __syncthreads();

    int nsteps = K >> 4;
    for (int s = 0; s < nsteps; s++) {
        int cur = s & 1;
        int has_next = (s + 1 < nsteps);

        if (has_next) {
            const float* ap = aPtr + (s + 1) * 16;
            const float* bp = bPtr + (size_t)(s + 1) * 16 * NPIX;
            ra0 = *(const float4*)&ap[0];
            ra1 = *(const float4*)&ap[4];
            rb0 = *(const float4*)&bp[0];
            rb1 = *(const float4*)&bp[4];
        }

#pragma unroll
        for (int k8 = 0; k8 < 16; k8 += 8) {
            uint32_t af[2][4], bf[8][2];
#pragma unroll
            for (int mt = 0; mt < 2; mt++) {
                int r = wm + mt * 16 + g;
                af[mt][0] = As[cur][r    ][k8 + t];
                af[mt][1] = As[cur][r + 8][k8 + t];
                af[mt][2] = As[cur][r    ][k8 + t + 4];
                af[mt][3] = As[cur][r + 8][k8 + t + 4];
            }
#pragma unroll
            for (int nt = 0; nt < 8; nt++) {
                int c = wn + nt * 8 + g;
                bf[nt][0] = Bs[cur][k8 + t    ][c];
                bf[nt][1] = Bs[cur][k8 + t + 4][c];
            }
#pragma unroll
            for (int mt = 0; mt < 2; mt++)
#pragma unroll
                for (int nt = 0; nt < 8; nt++)
                    mma_tf32(acc[mt][nt],
                             af[mt][0], af[mt][1], af[mt][2], af[mt][3],
                             bf[nt][0], bf[nt][1]);
        }

        if (has_next) {
            int nxt = cur ^ 1;
            *(uint4*)&As[nxt][arow][akb]     = cvt4(ra0);
            *(uint4*)&As[nxt][arow][akb + 4] = cvt4(ra1);
            *(uint4*)&Bs[nxt][bk][bnb]       = cvt4(rb0);
            *(uint4*)&Bs[nxt][bk][bnb + 4]   = cvt4(rb1);
            __syncthreads();
        }
    }

#pragma unroll
    for (int mt = 0; mt < 2; mt++) {
        int r0 = wm + mt * 16 + g;
#pragma unroll
        for (int nt = 0; nt < 8; nt++) {
            int c0 = wn + nt * 8 + 2 * t;
            float2 lo = {acc[mt][nt][0], acc[mt][nt][1]};
            float2 hi = {acc[mt][nt][2], acc[mt][nt][3]};
            *(float2*)&Cb[(size_t)r0       * NPIX + c0] = lo;
            *(float2*)&Cb[(size_t)(r0 + 8) * NPIX + c0] = hi;
        }
    }
}

// ---------------------------------------------------------------------------
// gemm2: pure cp.async 3-stage pipeline. Operands are PRE-ROUNDED tf32 floats
// (W2 by ctxw2, q by ctx_part writeback) so fragments feed mma directly.
// C[b] = A[b](rows by*128.., 128x128) * B[b](128 x 4096). Same warp layout.
// ---------------------------------------------------------------------------
__global__ void __launch_bounds__(256)
gemm2_async(const float* __restrict__ A, const float* __restrict__ B,
            float* __restrict__ C)
{
    extern __shared__ uint32_t sm[];
    const int K = HID;                  // 128

    int b = blockIdx.z;
    const float* Ab = A + (size_t)b * (CDIM * HID) + (size_t)(blockIdx.y * 128) * K;
    const float* Bb = B + (size_t)b * (256 * NPIX) + blockIdx.x * 128;
    float*       Cb = C + (size_t)b * (CDIM * NPIX) + (size_t)(blockIdx.y * 128) * NPIX
                        + blockIdx.x * 128;

    int tid  = threadIdx.x;
    int lane = tid & 31, warp = tid >> 5;
    int g = lane >> 2, t = lane & 3;
    int wm = (warp >> 1) * 32;
    int wn = (warp & 1) * 64;

    uint32_t smb = (uint32_t)__cvta_generic_to_shared(sm);
    int nsteps = K >> 4;                // 8

    // A: 128 rows x 16 k per stage = 512 16B-chunks; thread does 2.
    // chunk c: row = c>>2, seg = c&3 -> smem u32 off row*PAD + seg*4 (80B rows, aligned)
    // B: 16 rows x 128 n per stage = 512 chunks; row = c>>5, cs = c&31
    //    smem u32 off G2_ASZ + row*BPITCH + cs*4 (544B rows, aligned)
#define G2_ISSUE(s)                                                            \
    do {                                                                       \
        if ((s) < nsteps) {                                                    \
            uint32_t stb_ = smb + (uint32_t)((s) % G2_NST) * (G2_STG * 4);     \
            _Pragma("unroll")                                                  \
            for (int i_ = 0; i_ < 2; i_++) {                                   \
                int c_ = tid + i_ * 256;                                       \
                int ar_ = c_ >> 2, as_ = c_ & 3;                               \
                CP_ASYNC16(stb_ + (uint32_t)(ar_ * PAD + as_ * 4) * 4,         \
                           Ab + (size_t)ar_ * K + (s) * 16 + as_ * 4);         \
                int br_ = c_ >> 5, bc_ = c_ & 31;                              \
                CP_ASYNC16(stb_ + (uint32_t)(G2_ASZ + br_ * BPITCH + bc_ * 4) * 4, \
                           Bb + (size_t)((s) * 16 + br_) * NPIX + bc_ * 4);    \
            }                                                                  \
        }                                                                      \
        CP_COMMIT();                                                           \
    } while (0)

    G2_ISSUE(0);
    G2_ISSUE(1);

    float acc[2][8][4] = {};

    for (int s = 0; s < nsteps; s++) {
        CP_WAIT1();                     // stage s resident
        __syncthreads();                // stage (s+2)%3 free of prior readers
        G2_ISSUE(s + 2);

        const uint32_t* As = sm + (s % G2_NST) * G2_STG;
        const uint32_t* Bs = As + G2_ASZ;

#pragma unroll
        for (int k8 = 0; k8 < 16; k8 += 8) {
            uint32_t af[2][4], bf[8][2];
#pragma unroll
            for (int mt = 0; mt < 2; mt++) {
                int r = wm + mt * 16 + g;
                af[mt][0] = As[r * PAD + k8 + t];
                af[mt][1] = As[(r + 8) * PAD + k8 + t];
                af[mt][2] = As[r * PAD + k8 + t + 4];
                af[mt][3] = As[(r + 8) * PAD + k8 + t + 4];
            }
#pragma unroll
            for (int nt = 0; nt < 8; nt++) {
                int c = wn + nt * 8 + g;
                bf[nt][0] = Bs[(k8 + t) * BPITCH + c];
                bf[nt][1] = Bs[(k8 + t + 4) * BPITCH + c];
            }
#pragma unroll
            for (int mt = 0; mt < 2; mt++)
#pragma unroll
                for (int nt = 0; nt < 8; nt++)
                    mma_tf32(acc[mt][nt],
                             af[mt][0], af[mt][1], af[mt][2], af[mt][3],
                             bf[nt][0], bf[nt][1]);
        }
        __syncthreads();                // done reading stage s before it is refilled
    }

#pragma unroll
    for (int mt = 0; mt < 2; mt++) {
        int r0 = wm + mt * 16 + g;
#pragma unroll
        for (int nt = 0; nt < 8; nt++) {
            int c0 = wn + nt * 8 + 2 * t;
            float2 lo = {acc[mt][nt][0], acc[mt][nt][1]};
            float2 hi = {acc[mt][nt][2], acc[mt][nt][3]};
            *(float2*)&Cb[(size_t)r0       * NPIX + c0] = lo;
            *(float2*)&Cb[(size_t)(r0 + 8) * NPIX + c0] = hi;
        }
    }
#undef G2_ISSUE
}

// ---------------------------------------------------------------------------
// Row stats for softmax over n: per q-row {max, 1/sum(exp(x-max))}.
// ---------------------------------------------------------------------------
__global__ void stats_kernel()
{
    int r = blockIdx.x;                 // 0..2047
    int b = r >> 7, q = r & 127;
    const float* row = g_qkv + (size_t)b * 256 * NPIX + (size_t)q * NPIX;
    int tid = threadIdx.x;

    float v[16];
    float m = -1e30f;
#pragma unroll
    for (int i = 0; i < 16; i++) { v[i] = row[tid + i * 256]; m = fmaxf(m, v[i]); }

    __shared__ float red[8];
#pragma unroll
    for (int o = 16; o > 0; o >>= 1) m = fmaxf(m, __shfl_xor_sync(~0u, m, o));
    if ((tid & 31) == 0) red[tid >> 5] = m;
    __syncthreads();
    m = red[0];
#pragma unroll
    for (int i = 1; i < 8; i++) m = fmaxf(m, red[i]);
    __syncthreads();

    float s = 0.f;
#pragma unroll
    for (int i = 0; i < 16; i++) s += __expf(v[i] - m);
#pragma unroll
    for (int o = 16; o > 0; o >>= 1) s += __shfl_xor_sync(~0u, s, o);
    if ((tid & 31) == 0) red[tid >> 5] = s;
    __syncthreads();
    if (tid == 0) {
        s = red[0];
#pragma unroll
        for (int i = 1; i < 8; i++) s += red[i];
        g_stats[r] = make_float2(m, 1.0f / s);
    }
}

// ---------------------------------------------------------------------------
// Fused: softmax-n applied on load (tf32-rounded copy written back for gemm2)
// + per-column softmax over d + partial context via tf32 MMA.
// One block per (b, h, chunk-group of 4x128 n).
// ---------------------------------------------------------------------------
__global__ void __launch_bounds__(256) ctx_part_kernel()
{
    int bid = blockIdx.x;               // 0..511
    int p   = bid & (NGRP - 1);
    int bh  = bid >> 3;
    int b   = bh >> 2, h = bh & 3;

    float* qp_base = g_qkv + ((size_t)b * 256 + h * DHEAD) * NPIX;
    const float* vp_base = g_qkv + ((size_t)b * 256 + 128 + h * DHEAD) * NPIX;

    __shared__ float kst[DHEAD][CPITCH];
    __shared__ float vst[DHEAD][CPITCH];

    int tid = threadIdx.x;
    int lane = tid & 31, warp = tid >> 5;
    int g = lane >> 2, t = lane & 3;
    int mrow = (warp >> 2) * 16;
    int ncol = (warp & 3) * 8;

    float acc[4] = {};

    for (int c4 = 0; c4 < 4; c4++) {
        int n0 = (p * 4 + c4) * CHW;
        if (c4) __syncthreads();        // smem reuse guard

#pragma unroll
        for (int r = 0; r < 4; r++) {
            int idx = tid + r * 256;
            int row = idx >> 5;         // d 0..31
            int col = (idx & 31) * 4;
            float2 st = g_stats[(b << 7) + (h << 5) + row];
            float4 qv = *(const float4*)&qp_base[(size_t)row * NPIX + n0 + col];
            float4 nq = normexp4(qv, st);
            *(float4*)&kst[row][col] = nq;          // full precision for ctx
            uint4 rq = cvt4(nq);                     // tf32-rounded for gemm2
            *(uint4*)&qp_base[(size_t)row * NPIX + n0 + col] = rq;
            *(float4*)&vst[row][col] = *(const float4*)&vp_base[(size_t)row * NPIX + n0 + col];
        }
        __syncthreads();

        // per-column softmax over d
        if (tid < CHW) {
            float e[DHEAD];
            float m = -1e30f;
#pragma unroll
            for (int d = 0; d < DHEAD; d++) { e[d] = kst[d][tid]; m = fmaxf(m, e[d]); }
            float s = 0.f;
#pragma unroll
            for (int d = 0; d < DHEAD; d++) { e[d] = __expf(e[d] - m); s += e[d]; }
            float inv = 1.0f / s;
#pragma unroll
            for (int d = 0; d < DHEAD; d++) kst[d][tid] = e[d] * inv;
        }
        __syncthreads();

#pragma unroll
        for (int k8 = 0; k8 < CHW; k8 += 8) {
            uint32_t a0 = f2tf32(kst[mrow + g    ][k8 + t]);
            uint32_t a1 = f2tf32(kst[mrow + g + 8][k8 + t]);
            uint32_t a2 = f2tf32(kst[mrow + g    ][k8 + t + 4]);
            uint32_t a3 = f2tf32(kst[mrow + g + 8][k8 + t + 4]);
            uint32_t b0 = f2tf32(vst[ncol + g][k8 + t]);
            uint32_t b1 = f2tf32(vst[ncol + g][k8 + t + 4]);
            mma_tf32(acc, a0, a1, a2, a3, b0, b1);
        }
    }

    float* pp = g_ctxp + ((size_t)bh * NGRP + p) * 1024;
    float2 lo = {acc[0], acc[1]};
    float2 hi = {acc[2], acc[3]};
    *(float2*)&pp[(mrow + g    ) * DHEAD + ncol + 2 * t] = lo;
    *(float2*)&pp[(mrow + g + 8) * DHEAD + ncol + 2 * t] = hi;
}

// ---------------------------------------------------------------------------
// Merged: reduce ctx partials (fixed order) + compose W2 (stored tf32-rounded).
// 4 blocks per (b,h); each handles 64 o-rows. Reduce is redundant but L2-cheap.
// ---------------------------------------------------------------------------
__global__ void __launch_bounds__(256) ctxw2_kernel(const float* __restrict__ w_out)
{
    int bid = blockIdx.x;               // 0..255
    int bh  = bid >> 2;
    int qo  = bid & 3;
    int b   = bh >> 2, h = bh & 3;

    __shared__ float ctx[1024];         // [k][v] 32x32
    int tid = threadIdx.x;
    const float* base = g_ctxp + (size_t)bh * (NGRP * 1024);

#pragma unroll
    for (int j = 0; j < 4; j++) {
        int e = tid + j * 256;
        float s = 0.f;
#pragma unroll
        for (int p = 0; p < NGRP; p++) s += base[p * 1024 + e];
        ctx[e] = s;
    }
    __syncthreads();

    int o  = qo * 64 + (tid >> 2);      // 64 o-rows per block
    int k0 = (tid & 3) * 8;             // 8 kk per thread

    float wrow[32];
#pragma unroll
    for (int v = 0; v < 32; v++) wrow[v] = w_out[o * HID + h * DHEAD + v];

    float* w2p = g_W2 + ((size_t)b * CDIM + o) * HID + h * DHEAD;
#pragma unroll
    for (int kk = 0; kk < 8; kk++) {
        float s = 0.f;
#pragma unroll
        for (int v = 0; v < 32; v++) s = fmaf(wrow[v], ctx[(k0 + kk) * 32 + v], s);
        w2p[k0 + kk] = __uint_as_float(f2tf32(s));   // pre-rounded for gemm2
    }
}

// ---------------------------------------------------------------------------
extern "C" void kernel_launch(void* const* d_in, const int* in_sizes, int n_in,
                              void* d_out, int out_size)
{
    const float* x     = (const float*)d_in[0];
    const float* w_qkv = (const float*)d_in[1];
    const float* w_out = (const float*)d_in[2];
    float*       out   = (float*)d_out;

    float *qkv_p, *w2_p;
    cudaGetSymbolAddress((void**)&qkv_p, g_qkv);
    cudaGetSymbolAddress((void**)&w2_p,  g_W2);

    cudaFuncSetAttribute(gemm2_async, cudaFuncAttributeMaxDynamicSharedMemorySize, G2_SMEM);

    dim3 gg(NPIX / 128, 2, BATCH);

    // 1) q and v projections (raw q stored; skip unused k_proj rows)
    gemm_tf32<<<gg, 256>>>(w_qkv, x, qkv_p, CDIM,
                           0, (size_t)CDIM * NPIX, (size_t)256 * NPIX, 256);
    // 2) per-row softmax-n stats
    stats_kernel<<<BATCH * HID, 256>>>();
    // 3) fused softmax-n (tf32-rounded writeback) + softmax-d + partial ctx
    ctx_part_kernel<<<BATCH * NHEADS * NGRP, 256>>>();
    // 4) merged reduce + W2 compose (W2 tf32-rounded)
    ctxw2_kernel<<<BATCH * NHEADS * 4, 256>>>(w_out);
    // 5) y = W2 @ normexp(q): pure cp.async GEMM on pre-rounded operands
    gemm2_async<<<gg, 256, G2_SMEM>>>(w2_p, qkv_p, out);
}

// round 16
// speedup vs baseline: 1.4192x; 1.0387x over previous
#include <cuda_runtime.h>
#include <math.h>
#include <stdint.h>

#define BATCH  16
#define CDIM   256
#define NPIX   4096
#define NHEADS 4
#define DHEAD  32
#define HID    128
#define CHW    128
#define NGRP   8             // chunk-groups per (b,h); 4 chunks of 128 each
#define PAD    20            // As pitch: frag bank = (20g+t)%32, all 32 distinct
#define BPITCH 136           // Bs pitch: 136%32==8 -> frag bank = 8t+g, all 32 distinct
#define CPITCH 132           // ctx smem pitch

// gemm2 cp.async pipeline geometry
#define G2_NST 3
#define G2_ASZ (128 * PAD)               // 2560 u32 per stage
#define G2_BSZ (16 * BPITCH)             // 2176 u32 per stage
#define G2_STG (G2_ASZ + G2_BSZ)         // 4736 u32
#define G2_SMEM (G2_NST * G2_STG * 4)    // 56832 bytes

// Scratch (device globals: allocation-free per harness rules)
__device__ float  g_qkv  [BATCH * 256 * NPIX];       // rows 0-127 = q, 128-255 = v
__device__ float  g_ctxp [BATCH * NHEADS * NGRP * DHEAD * DHEAD];  // 2 MB partials
__device__ float  g_W2   [BATCH * CDIM * HID];       // stored tf32-rounded
__device__ float2 g_statp[BATCH * HID * 32];         // per (row, n-chunk) {max, sumexp}
__device__ float2 g_stats[BATCH * HID];              // per q-row {max, 1/sumexp}

__device__ __forceinline__ uint32_t f2tf32(float f)
{
    uint32_t u;
    asm("cvt.rna.tf32.f32 %0, %1;" : "=r"(u) : "f"(f));
    return u;
}

__device__ __forceinline__ void mma_tf32(float c[4],
    uint32_t a0, uint32_t a1, uint32_t a2, uint32_t a3,
    uint32_t b0, uint32_t b1)
{
    asm volatile(
        "mma.sync.aligned.m16n8k8.row.col.f32.tf32.tf32.f32 "
        "{%0,%1,%2,%3}, {%4,%5,%6,%7}, {%8,%9}, {%0,%1,%2,%3};"
        : "+f"(c[0]), "+f"(c[1]), "+f"(c[2]), "+f"(c[3])
        : "r"(a0), "r"(a1), "r"(a2), "r"(a3), "r"(b0), "r"(b1));
}

__device__ __forceinline__ uint4 cvt4(float4 v)
{
    uint4 u;
    u.x = f2tf32(v.x); u.y = f2tf32(v.y); u.z = f2tf32(v.z); u.w = f2tf32(v.w);
    return u;
}

__device__ __forceinline__ float4 normexp4(float4 v, float2 st)
{
    float4 r;
    r.x = __expf(v.x - st.x) * st.y;
    r.y = __expf(v.y - st.x) * st.y;
    r.z = __expf(v.z - st.x) * st.y;
    r.w = __expf(v.w - st.x) * st.y;
    return r;
}

#define CP_ASYNC16(dst, src) \
    asm volatile("cp.async.ca.shared.global [%0], [%1], 16;" :: "r"(dst), "l"(src))
#define CP_COMMIT() asm volatile("cp.async.commit_group;")
#define CP_WAIT1()  asm volatile("cp.async.wait_group 1;")

// ---------------------------------------------------------------------------
// gemm1: tf32 tensor-core GEMM, register-staged double buffer (proven R7),
// plus fused softmax-n partial stats in the epilogue (q blocks only).
// Block tile 128x128, BK=16, 8 warps (4m x 2n), warp tile 32x64.
// ---------------------------------------------------------------------------
__global__ void __launch_bounds__(256)
gemm_tf32(const float* __restrict__ A, const float* __restrict__ B,
          float* __restrict__ C, int K,
          size_t sA, size_t sB, size_t sC, int aJump,
          float2* __restrict__ statp)
{
    __shared__ uint32_t As[2][128][PAD];      // [buf][m][k]
    __shared__ uint32_t Bs[2][16][BPITCH];    // [buf][k][n]
    __shared__ float    srow[128][2];         // stats cross-warp scratch

    int b = blockIdx.z;
    const float* Ab = A + (size_t)b * sA + (size_t)(blockIdx.y * aJump) * K;
    const float* Bb = B + (size_t)b * sB + blockIdx.x * 128;
    float*       Cb = C + (size_t)b * sC + (size_t)(blockIdx.y * 128) * NPIX + blockIdx.x * 128;

    int tid  = threadIdx.x;
    int lane = tid & 31, warp = tid >> 5;
    int g = lane >> 2, t = lane & 3;
    int wm = (warp >> 1) * 32;
    int wn = (warp & 1) * 64;

    int arow = tid >> 1, akb = (tid & 1) * 8;     // A loader: 128 rows x 16 k
    int bk   = tid >> 4, bnb = (tid & 15) * 8;    // B loader: 16 k x 128 n

    const float* aPtr = &Ab[(size_t)arow * K + akb];
    const float* bPtr = &Bb[(size_t)bk * NPIX + bnb];

    float acc[2][8][4] = {};
    float4 ra0, ra1, rb0, rb1;

    ra0 = *(const float4*)&aPtr[0];
    ra1 = *(const float4*)&aPtr[4];
    rb0 = *(const float4*)&bPtr[0];
    rb1 = *(const float4*)&bPtr[4];
    *(uint4*)&As[0][arow][akb]     = cvt4(ra0);
    *(uint4*)&As[0][arow][akb + 4] = cvt4(ra1);
    *(uint4*)&Bs[0][bk][bnb]       = cvt4(rb0);
    *(uint4*)&Bs[0][bk][bnb + 4]   = cvt4(rb1);
    __syncthreads();

    int nsteps = K >> 4;
    for (int s = 0; s < nsteps; s++) {
        int cur = s & 1;
        int has_next = (s + 1 < nsteps);

        if (has_next) {
            const float* ap = aPtr + (s + 1) * 16;
            const float* bp = bPtr + (size_t)(s + 1) * 16 * NPIX;
            ra0 = *(const float4*)&ap[0];
            ra1 = *(const float4*)&ap[4];
            rb0 = *(const float4*)&bp[0];
            rb1 = *(const float4*)&bp[4];
        }

#pragma unroll
        for (int k8 = 0; k8 < 16; k8 += 8) {
            uint32_t af[2][4], bf[8][2];
#pragma unroll
            for (int mt = 0; mt < 2; mt++) {
                int r = wm + mt * 16 + g;
                af[mt][0] = As[cur][r    ][k8 + t];
                af[mt][1] = As[cur][r + 8][k8 + t];
                af[mt][2] = As[cur][r    ][k8 + t + 4];
                af[mt][3] = As[cur][r + 8][k8 + t + 4];
            }
#pragma unroll
            for (int nt = 0; nt < 8; nt++) {
                int c = wn + nt * 8 + g;
                bf[nt][0] = Bs[cur][k8 + t    ][c];
                bf[nt][1] = Bs[cur][k8 + t + 4][c];
            }
#pragma unroll
            for (int mt = 0; mt < 2; mt++)
#pragma unroll
                for (int nt = 0; nt < 8; nt++)
                    mma_tf32(acc[mt][nt],
                             af[mt][0], af[mt][1], af[mt][2], af[mt][3],
                             bf[nt][0], bf[nt][1]);
        }

        if (has_next) {
            int nxt = cur ^ 1;
            *(uint4*)&As[nxt][arow][akb]     = cvt4(ra0);
            *(uint4*)&As[nxt][arow][akb + 4] = cvt4(ra1);
            *(uint4*)&Bs[nxt][bk][bnb]       = cvt4(rb0);
            *(uint4*)&Bs[nxt][bk][bnb + 4]   = cvt4(rb1);
            __syncthreads();
        }
    }

#pragma unroll
    for (int mt = 0; mt < 2; mt++) {
        int r0 = wm + mt * 16 + g;
#pragma unroll
        for (int nt = 0; nt < 8; nt++) {
            int c0 = wn + nt * 8 + 2 * t;
            float2 lo = {acc[mt][nt][0], acc[mt][nt][1]};
            float2 hi = {acc[mt][nt][2], acc[mt][nt][3]};
            *(float2*)&Cb[(size_t)r0       * NPIX + c0] = lo;
            *(float2*)&Cb[(size_t)(r0 + 8) * NPIX + c0] = hi;
        }
    }

    // ---- fused softmax-n partial stats (q blocks: blockIdx.y == 0) ----
    if (statp != nullptr && blockIdx.y == 0) {
        __syncthreads();    // As/Bs done; srow safe

        // per-thread row-local max over 16 cols, 4 rows: [mt*2 + half]
        float mx[4];
#pragma unroll
        for (int mt = 0; mt < 2; mt++) {
            float m0 = -1e30f, m1 = -1e30f;
#pragma unroll
            for (int nt = 0; nt < 8; nt++) {
                m0 = fmaxf(m0, fmaxf(acc[mt][nt][0], acc[mt][nt][1]));
                m1 = fmaxf(m1, fmaxf(acc[mt][nt][2], acc[mt][nt][3]));
            }
            mx[mt * 2] = m0; mx[mt * 2 + 1] = m1;
        }
#pragma unroll
        for (int o = 1; o < 4; o <<= 1)
#pragma unroll
            for (int i = 0; i < 4; i++)
                mx[i] = fmaxf(mx[i], __shfl_xor_sync(~0u, mx[i], o));
        if (t == 0)
#pragma unroll
            for (int i = 0; i < 4; i++)
                srow[wm + (i >> 1) * 16 + g + (i & 1) * 8][warp & 1] = mx[i];
        __syncthreads();

        float rmax[4];
#pragma unroll
        for (int i = 0; i < 4; i++) {
            int row = wm + (i >> 1) * 16 + g + (i & 1) * 8;
            rmax[i] = fmaxf(srow[row][0], srow[row][1]);
        }
        __syncthreads();

        float sme[4] = {0.f, 0.f, 0.f, 0.f};
#pragma unroll
        for (int mt = 0; mt < 2; mt++)
#pragma unroll
            for (int nt = 0; nt < 8; nt++) {
                sme[mt * 2]     += __expf(acc[mt][nt][0] - rmax[mt * 2])
                                 + __expf(acc[mt][nt][1] - rmax[mt * 2]);
                sme[mt * 2 + 1] += __expf(acc[mt][nt][2] - rmax[mt * 2 + 1])
                                 + __expf(acc[mt][nt][3] - rmax[mt * 2 + 1]);
            }
#pragma unroll
        for (int o = 1; o < 4; o <<= 1)
#pragma unroll
            for (int i = 0; i < 4; i++)
                sme[i] += __shfl_xor_sync(~0u, sme[i], o);
        if (t == 0)
#pragma unroll
            for (int i = 0; i < 4; i++)
                srow[wm + (i >> 1) * 16 + g + (i & 1) * 8][warp & 1] = sme[i];
        __syncthreads();

        if (t == 0 && (warp & 1) == 0) {
#pragma unroll
            for (int i = 0; i < 4; i++) {
                int row = wm + (i >> 1) * 16 + g + (i & 1) * 8;
                statp[((size_t)b * HID + row) * 32 + blockIdx.x] =
                    make_float2(rmax[i], srow[row][0] + srow[row][1]);
            }
        }
    }
}

// ---------------------------------------------------------------------------
// Reduce the 32 per-chunk stats into {max, 1/sumexp} per q-row.
// One warp per row; max is exact, sums rescaled by exp(m_i - M).
// ---------------------------------------------------------------------------
__global__ void __launch_bounds__(256) stats_reduce()
{
    int row  = blockIdx.x * 8 + (threadIdx.x >> 5);   // 0..2047
    int lane = threadIdx.x & 31;

    float2 p = g_statp[(size_t)row * 32 + lane];
    float M = p.x;
#pragma unroll
    for (int o = 16; o > 0; o >>= 1) M = fmaxf(M, __shfl_xor_sync(~0u, M, o));
    float s = p.y * __expf(p.x - M);
#pragma unroll
    for (int o = 16; o > 0; o >>= 1) s += __shfl_xor_sync(~0u, s, o);
    if (lane == 0) g_stats[row] = make_float2(M, 1.0f / s);
}

// ---------------------------------------------------------------------------
// gemm2: pure cp.async 3-stage pipeline on PRE-ROUNDED tf32 operands.
// ---------------------------------------------------------------------------
__global__ void __launch_bounds__(256)
gemm2_async(const float* __restrict__ A, const float* __restrict__ B,
            float* __restrict__ C)
{
    extern __shared__ uint32_t sm[];
    const int K = HID;                  // 128

    int b = blockIdx.z;
    const float* Ab = A + (size_t)b * (CDIM * HID) + (size_t)(blockIdx.y * 128) * K;
    const float* Bb = B + (size_t)b * (256 * NPIX) + blockIdx.x * 128;
    float*       Cb = C + (size_t)b * (CDIM * NPIX) + (size_t)(blockIdx.y * 128) * NPIX
                        + blockIdx.x * 128;

    int tid  = threadIdx.x;
    int lane = tid & 31, warp = tid >> 5;
    int g = lane >> 2, t = lane & 3;
    int wm = (warp >> 1) * 32;
    int wn = (warp & 1) * 64;

    uint32_t smb = (uint32_t)__cvta_generic_to_shared(sm);
    int nsteps = K >> 4;                // 8

#define G2_ISSUE(s)                                                            \
    do {                                                                       \
        if ((s) < nsteps) {                                                    \
            uint32_t stb_ = smb + (uint32_t)((s) % G2_NST) * (G2_STG * 4);     \
            _Pragma("unroll")                                                  \
            for (int i_ = 0; i_ < 2; i_++) {                                   \
                int c_ = tid + i_ * 256;                                       \
                int ar_ = c_ >> 2, as_ = c_ & 3;                               \
                CP_ASYNC16(stb_ + (uint32_t)(ar_ * PAD + as_ * 4) * 4,         \
                           Ab + (size_t)ar_ * K + (s) * 16 + as_ * 4);         \
                int br_ = c_ >> 5, bc_ = c_ & 31;                              \
                CP_ASYNC16(stb_ + (uint32_t)(G2_ASZ + br_ * BPITCH + bc_ * 4) * 4, \
                           Bb + (size_t)((s) * 16 + br_) * NPIX + bc_ * 4);    \
            }                                                                  \
        }                                                                      \
        CP_COMMIT();                                                           \
    } while (0)

    G2_ISSUE(0);
    G2_ISSUE(1);

    float acc[2][8][4] = {};

    for (int s = 0; s < nsteps; s++) {
        CP_WAIT1();
        __syncthreads();
        G2_ISSUE(s + 2);

        const uint32_t* As = sm + (s % G2_NST) * G2_STG;
        const uint32_t* Bs = As + G2_ASZ;

#pragma unroll
        for (int k8 = 0; k8 < 16; k8 += 8) {
            uint32_t af[2][4], bf[8][2];
#pragma unroll
            for (int mt = 0; mt < 2; mt++) {
                int r = wm + mt * 16 + g;
                af[mt][0] = As[r * PAD + k8 + t];
                af[mt][1] = As[(r + 8) * PAD + k8 + t];
                af[mt][2] = As[r * PAD + k8 + t + 4];
                af[mt][3] = As[(r + 8) * PAD + k8 + t + 4];
            }
#pragma unroll
            for (int nt = 0; nt < 8; nt++) {
                int c = wn + nt * 8 + g;
                bf[nt][0] = Bs[(k8 + t) * BPITCH + c];
                bf[nt][1] = Bs[(k8 + t + 4) * BPITCH + c];
            }
#pragma unroll
            for (int mt = 0; mt < 2; mt++)
#pragma unroll
                for (int nt = 0; nt < 8; nt++)
                    mma_tf32(acc[mt][nt],
                             af[mt][0], af[mt][1], af[mt][2], af[mt][3],
                             bf[nt][0], bf[nt][1]);
        }
        __syncthreads();
    }

#pragma unroll
    for (int mt = 0; mt < 2; mt++) {
        int r0 = wm + mt * 16 + g;
#pragma unroll
        for (int nt = 0; nt < 8; nt++) {
            int c0 = wn + nt * 8 + 2 * t;
            float2 lo = {acc[mt][nt][0], acc[mt][nt][1]};
            float2 hi = {acc[mt][nt][2], acc[mt][nt][3]};
            *(float2*)&Cb[(size_t)r0       * NPIX + c0] = lo;
            *(float2*)&Cb[(size_t)(r0 + 8) * NPIX + c0] = hi;
        }
    }
#undef G2_ISSUE
}

// ---------------------------------------------------------------------------
// Fused: softmax-n applied on load (tf32-rounded copy written back for gemm2)
// + per-column softmax over d + partial context via tf32 MMA.
// ---------------------------------------------------------------------------
__global__ void __launch_bounds__(256) ctx_part_kernel()
{
    int bid = blockIdx.x;               // 0..511
    int p   = bid & (NGRP - 1);
    int bh  = bid >> 3;
    int b   = bh >> 2, h = bh & 3;

    float* qp_base = g_qkv + ((size_t)b * 256 + h * DHEAD) * NPIX;
    const float* vp_base = g_qkv + ((size_t)b * 256 + 128 + h * DHEAD) * NPIX;

    __shared__ float kst[DHEAD][CPITCH];
    __shared__ float vst[DHEAD][CPITCH];

    int tid = threadIdx.x;
    int lane = tid & 31, warp = tid >> 5;
    int g = lane >> 2, t = lane & 3;
    int mrow = (warp >> 2) * 16;
    int ncol = (warp & 3) * 8;

    float acc[4] = {};

    for (int c4 = 0; c4 < 4; c4++) {
        int n0 = (p * 4 + c4) * CHW;
        if (c4) __syncthreads();

#pragma unroll
        for (int r = 0; r < 4; r++) {
            int idx = tid + r * 256;
            int row = idx >> 5;         // d 0..31
            int col = (idx & 31) * 4;
            float2 st = g_stats[(b << 7) + (h << 5) + row];
            float4 qv = *(const float4*)&qp_base[(size_t)row * NPIX + n0 + col];
            float4 nq = normexp4(qv, st);
            *(float4*)&kst[row][col] = nq;
            uint4 rq = cvt4(nq);
            *(uint4*)&qp_base[(size_t)row * NPIX + n0 + col] = rq;
            *(float4*)&vst[row][col] = *(const float4*)&vp_base[(size_t)row * NPIX + n0 + col];
        }
        __syncthreads();

        if (tid < CHW) {
            float e[DHEAD];
            float m = -1e30f;
#pragma unroll
            for (int d = 0; d < DHEAD; d++) { e[d] = kst[d][tid]; m = fmaxf(m, e[d]); }
            float s = 0.f;
#pragma unroll
            for (int d = 0; d < DHEAD; d++) { e[d] = __expf(e[d] - m); s += e[d]; }
            float inv = 1.0f / s;
#pragma unroll
            for (int d = 0; d < DHEAD; d++) kst[d][tid] = e[d] * inv;
        }
        __syncthreads();

#pragma unroll
        for (int k8 = 0; k8 < CHW; k8 += 8) {
            uint32_t a0 = f2tf32(kst[mrow + g    ][k8 + t]);
            uint32_t a1 = f2tf32(kst[mrow + g + 8][k8 + t]);
            uint32_t a2 = f2tf32(kst[mrow + g    ][k8 + t + 4]);
            uint32_t a3 = f2tf32(kst[mrow + g + 8][k8 + t + 4]);
            uint32_t b0 = f2tf32(vst[ncol + g][k8 + t]);
            uint32_t b1 = f2tf32(vst[ncol + g][k8 + t + 4]);
            mma_tf32(acc, a0, a1, a2, a3, b0, b1);
        }
    }

    float* pp = g_ctxp + ((size_t)bh * NGRP + p) * 1024;
    float2 lo = {acc[0], acc[1]};
    float2 hi = {acc[2], acc[3]};
    *(float2*)&pp[(mrow + g    ) * DHEAD + ncol + 2 * t] = lo;
    *(float2*)&pp[(mrow + g + 8) * DHEAD + ncol + 2 * t] = hi;
}

// ---------------------------------------------------------------------------
// Merged: reduce ctx partials + compose W2 (tf32-rounded). One block per (b,h).
// w_out head-slice staged in smem (coalesced); thread o keeps its row in regs.
// ---------------------------------------------------------------------------
__global__ void __launch_bounds__(256) ctxw2_kernel(const float* __restrict__ w_out)
{
    int bh = blockIdx.x;                // b*4 + h
    int b  = bh >> 2, h = bh & 3;

    __shared__ float ctx[1024];         // [k][v] 32x32
    __shared__ float ws[256][33];       // w_out[:, h*32 : h*32+32], pitch 33
    int tid = threadIdx.x;
    const float* base = g_ctxp + (size_t)bh * (NGRP * 1024);

#pragma unroll
    for (int j = 0; j < 4; j++) {
        int e = tid + j * 256;
        float s = 0.f;
#pragma unroll
        for (int p = 0; p < NGRP; p++) s += base[p * 1024 + e];
        ctx[e] = s;
    }
    // coalesced w_out slice load: 8192 floats
#pragma unroll
    for (int j = 0; j < 32; j++) {
        int i = tid + j * 256;          // 0..8191
        int o = i >> 5, v = i & 31;
        ws[o][v] = w_out[o * HID + h * DHEAD + v];
    }
    __syncthreads();

    int o = tid;                        // 0..255
    float wrow[32];
#pragma unroll
    for (int v = 0; v < 32; v++) wrow[v] = ws[o][v];   // lane-distinct banks

    float* w2p = g_W2 + ((size_t)b * CDIM + o) * HID + h * DHEAD;
#pragma unroll
    for (int kk = 0; kk < 32; kk++) {
        float s = 0.f;
#pragma unroll
        for (int v = 0; v < 32; v++) s = fmaf(wrow[v], ctx[kk * 32 + v], s);   // broadcast
        w2p[kk] = __uint_as_float(f2tf32(s));   // pre-rounded for gemm2
    }
}

// ---------------------------------------------------------------------------
extern "C" void kernel_launch(void* const* d_in, const int* in_sizes, int n_in,
                              void* d_out, int out_size)
{
    const float* x     = (const float*)d_in[0];
    const float* w_qkv = (const float*)d_in[1];
    const float* w_out = (const float*)d_in[2];
    float*       out   = (float*)d_out;

    float  *qkv_p, *w2_p;
    float2 *stp_p;
    cudaGetSymbolAddress((void**)&qkv_p, g_qkv);
    cudaGetSymbolAddress((void**)&w2_p,  g_W2);
    cudaGetSymbolAddress((void**)&stp_p, g_statp);

    cudaFuncSetAttribute(gemm2_async, cudaFuncAttributeMaxDynamicSharedMemorySize, G2_SMEM);

    dim3 gg(NPIX / 128, 2, BATCH);

    // 1) q and v projections + fused softmax-n partial stats (q blocks)
    gemm_tf32<<<gg, 256>>>(w_qkv, x, qkv_p, CDIM,
                           0, (size_t)CDIM * NPIX, (size_t)256 * NPIX, 256, stp_p);
    // 2) tiny stats reduce: {max, 1/sumexp} per q-row
    stats_reduce<<<BATCH * HID / 8, 256>>>();
    // 3) fused softmax-n (tf32-rounded writeback) + softmax-d + partial ctx
    ctx_part_kernel<<<BATCH * NHEADS * NGRP, 256>>>();
    // 4) merged reduce + W2 compose (smem-staged w_out)
    ctxw2_kernel<<<BATCH * NHEADS, 256>>>(w_out);
    // 5) y = W2 @ normexp(q): pure cp.async GEMM on pre-rounded operands
    gemm2_async<<<gg, 256, G2_SMEM>>>(w2_p, qkv_p, out);
}

// round 17
// speedup vs baseline: 1.5110x; 1.0647x over previous
#include <cuda_runtime.h>
#include <math.h>
#include <stdint.h>

#define BATCH  16
#define CDIM   256
#define NPIX   4096
#define NHEADS 4
#define DHEAD  32
#define HID    128
#define CHW    128
#define NGRP   8             // chunk-groups per (b,h); 4 chunks of 128 each
#define PAD    20            // As pitch: frag bank = (20g+t)%32, all 32 distinct
#define BPITCH 136           // Bs pitch: 136%32==8 -> frag bank = 8t+g, all 32 distinct
#define CPITCH 132           // ctx smem pitch

// cp.async pipeline geometry (shared by both GEMMs)
#define G2_NST 3
#define G2_ASZ (128 * PAD)               // 2560 u32 per stage
#define G2_BSZ (16 * BPITCH)             // 2176 u32 per stage
#define G2_STG (G2_ASZ + G2_BSZ)         // 4736 u32
#define G2_SMEM (G2_NST * G2_STG * 4)    // 56832 bytes

// Scratch (device globals: allocation-free per harness rules)
__device__ float  g_qkv  [BATCH * 256 * NPIX];       // rows 0-127 = q, 128-255 = v
__device__ float  g_ctxp [BATCH * NHEADS * NGRP * DHEAD * DHEAD];  // 2 MB partials
__device__ float  g_W2   [BATCH * CDIM * HID];       // stored tf32-rounded
__device__ float2 g_statp[BATCH * HID * 32];         // per (row, n-chunk) {max, sumexp}
__device__ float2 g_stats[BATCH * HID];              // per q-row {max, 1/sumexp}

__device__ __forceinline__ uint32_t f2tf32(float f)
{
    uint32_t u;
    asm("cvt.rna.tf32.f32 %0, %1;" : "=r"(u) : "f"(f));
    return u;
}

__device__ __forceinline__ void mma_tf32(float c[4],
    uint32_t a0, uint32_t a1, uint32_t a2, uint32_t a3,
    uint32_t b0, uint32_t b1)
{
    asm volatile(
        "mma.sync.aligned.m16n8k8.row.col.f32.tf32.tf32.f32 "
        "{%0,%1,%2,%3}, {%4,%5,%6,%7}, {%8,%9}, {%0,%1,%2,%3};"
        : "+f"(c[0]), "+f"(c[1]), "+f"(c[2]), "+f"(c[3])
        : "r"(a0), "r"(a1), "r"(a2), "r"(a3), "r"(b0), "r"(b1));
}

__device__ __forceinline__ uint4 cvt4(float4 v)
{
    uint4 u;
    u.x = f2tf32(v.x); u.y = f2tf32(v.y); u.z = f2tf32(v.z); u.w = f2tf32(v.w);
    return u;
}

__device__ __forceinline__ float4 normexp4(float4 v, float2 st)
{
    float4 r;
    r.x = __expf(v.x - st.x) * st.y;
    r.y = __expf(v.y - st.x) * st.y;
    r.z = __expf(v.z - st.x) * st.y;
    r.w = __expf(v.w - st.x) * st.y;
    return r;
}

#define CP_ASYNC16(dst, src) \
    asm volatile("cp.async.ca.shared.global [%0], [%1], 16;" :: "r"(dst), "l"(src))
#define CP_COMMIT() asm volatile("cp.async.commit_group;")
#define CP_WAIT1()  asm volatile("cp.async.wait_group 1;")

// issue helper shared by both GEMM kernels: per-stage A 128x16, B 16x128
#define GX_ISSUE(s, nsteps, Kdim)                                              \
    do {                                                                       \
        if ((s) < (nsteps)) {                                                  \
            uint32_t stb_ = smb + (uint32_t)((s) % G2_NST) * (G2_STG * 4);     \
            _Pragma("unroll")                                                  \
            for (int i_ = 0; i_ < 2; i_++) {                                   \
                int c_ = tid + i_ * 256;                                       \
                int ar_ = c_ >> 2, as_ = c_ & 3;                               \
                CP_ASYNC16(stb_ + (uint32_t)(ar_ * PAD + as_ * 4) * 4,         \
                           Ab + (size_t)ar_ * (Kdim) + (s) * 16 + as_ * 4);    \
                int br_ = c_ >> 5, bc_ = c_ & 31;                              \
                CP_ASYNC16(stb_ + (uint32_t)(G2_ASZ + br_ * BPITCH + bc_ * 4) * 4, \
                           Bb + (size_t)((s) * 16 + br_) * NPIX + bc_ * 4);    \
            }                                                                  \
        }                                                                      \
        CP_COMMIT();                                                           \
    } while (0)

// ---------------------------------------------------------------------------
// gemm1: cp.async 3-stage pipeline on RAW fp32 operands; cvt.rna at fragment
// load. A = w_qkv rows (blockIdx.y*aJump..), K=256. Fused softmax-n partial
// stats in the epilogue for q blocks (blockIdx.y == 0).
// Block tile 128x128, BK=16, 8 warps (4m x 2n), warp tile 32x64.
// ---------------------------------------------------------------------------
__global__ void __launch_bounds__(256)
gemm1_async(const float* __restrict__ A, const float* __restrict__ B,
            float* __restrict__ C, float2* __restrict__ statp, int aJump)
{
    extern __shared__ uint32_t sm[];
    __shared__ float srow[128][2];      // stats cross-warp scratch (static)
    const int K = CDIM;                 // 256

    int b = blockIdx.z;
    const float* Ab = A + (size_t)(blockIdx.y * aJump) * K;
    const float* Bb = B + (size_t)b * (CDIM * NPIX) + blockIdx.x * 128;
    float*       Cb = C + (size_t)b * (256 * NPIX) + (size_t)(blockIdx.y * 128) * NPIX
                        + blockIdx.x * 128;

    int tid  = threadIdx.x;
    int lane = tid & 31, warp = tid >> 5;
    int g = lane >> 2, t = lane & 3;
    int wm = (warp >> 1) * 32;
    int wn = (warp & 1) * 64;

    uint32_t smb = (uint32_t)__cvta_generic_to_shared(sm);
    int nsteps = K >> 4;                // 16

    GX_ISSUE(0, nsteps, K);
    GX_ISSUE(1, nsteps, K);

    float acc[2][8][4] = {};

    for (int s = 0; s < nsteps; s++) {
        CP_WAIT1();
        __syncthreads();
        GX_ISSUE(s + 2, nsteps, K);

        const uint32_t* As = sm + (s % G2_NST) * G2_STG;
        const uint32_t* Bs = As + G2_ASZ;

#pragma unroll
        for (int k8 = 0; k8 < 16; k8 += 8) {
            uint32_t af[2][4], bf[8][2];
#pragma unroll
            for (int mt = 0; mt < 2; mt++) {
                int r = wm + mt * 16 + g;
                af[mt][0] = f2tf32(__uint_as_float(As[r * PAD + k8 + t]));
                af[mt][1] = f2tf32(__uint_as_float(As[(r + 8) * PAD + k8 + t]));
                af[mt][2] = f2tf32(__uint_as_float(As[r * PAD + k8 + t + 4]));
                af[mt][3] = f2tf32(__uint_as_float(As[(r + 8) * PAD + k8 + t + 4]));
            }
#pragma unroll
            for (int nt = 0; nt < 8; nt++) {
                int c = wn + nt * 8 + g;
                bf[nt][0] = f2tf32(__uint_as_float(Bs[(k8 + t) * BPITCH + c]));
                bf[nt][1] = f2tf32(__uint_as_float(Bs[(k8 + t + 4) * BPITCH + c]));
            }
#pragma unroll
            for (int mt = 0; mt < 2; mt++)
#pragma unroll
                for (int nt = 0; nt < 8; nt++)
                    mma_tf32(acc[mt][nt],
                             af[mt][0], af[mt][1], af[mt][2], af[mt][3],
                             bf[nt][0], bf[nt][1]);
        }
        __syncthreads();
    }

#pragma unroll
    for (int mt = 0; mt < 2; mt++) {
        int r0 = wm + mt * 16 + g;
#pragma unroll
        for (int nt = 0; nt < 8; nt++) {
            int c0 = wn + nt * 8 + 2 * t;
            float2 lo = {acc[mt][nt][0], acc[mt][nt][1]};
            float2 hi = {acc[mt][nt][2], acc[mt][nt][3]};
            *(float2*)&Cb[(size_t)r0       * NPIX + c0] = lo;
            *(float2*)&Cb[(size_t)(r0 + 8) * NPIX + c0] = hi;
        }
    }

    // ---- fused softmax-n partial stats (q blocks: blockIdx.y == 0) ----
    if (blockIdx.y == 0) {
        __syncthreads();

        float mx[4];
#pragma unroll
        for (int mt = 0; mt < 2; mt++) {
            float m0 = -1e30f, m1 = -1e30f;
#pragma unroll
            for (int nt = 0; nt < 8; nt++) {
                m0 = fmaxf(m0, fmaxf(acc[mt][nt][0], acc[mt][nt][1]));
                m1 = fmaxf(m1, fmaxf(acc[mt][nt][2], acc[mt][nt][3]));
            }
            mx[mt * 2] = m0; mx[mt * 2 + 1] = m1;
        }
#pragma unroll
        for (int o = 1; o < 4; o <<= 1)
#pragma unroll
            for (int i = 0; i < 4; i++)
                mx[i] = fmaxf(mx[i], __shfl_xor_sync(~0u, mx[i], o));
        if (t == 0)
#pragma unroll
            for (int i = 0; i < 4; i++)
                srow[wm + (i >> 1) * 16 + g + (i & 1) * 8][warp & 1] = mx[i];
        __syncthreads();

        float rmax[4];
#pragma unroll
        for (int i = 0; i < 4; i++) {
            int row = wm + (i >> 1) * 16 + g + (i & 1) * 8;
            rmax[i] = fmaxf(srow[row][0], srow[row][1]);
        }
        __syncthreads();

        float sme[4] = {0.f, 0.f, 0.f, 0.f};
#pragma unroll
        for (int mt = 0; mt < 2; mt++)
#pragma unroll
            for (int nt = 0; nt < 8; nt++) {
                sme[mt * 2]     += __expf(acc[mt][nt][0] - rmax[mt * 2])
                                 + __expf(acc[mt][nt][1] - rmax[mt * 2]);
                sme[mt * 2 + 1] += __expf(acc[mt][nt][2] - rmax[mt * 2 + 1])
                                 + __expf(acc[mt][nt][3] - rmax[mt * 2 + 1]);
            }
#pragma unroll
        for (int o = 1; o < 4; o <<= 1)
#pragma unroll
            for (int i = 0; i < 4; i++)
                sme[i] += __shfl_xor_sync(~0u, sme[i], o);
        if (t == 0)
#pragma unroll
            for (int i = 0; i < 4; i++)
                srow[wm + (i >> 1) * 16 + g + (i & 1) * 8][warp & 1] = sme[i];
        __syncthreads();

        if (t == 0 && (warp & 1) == 0) {
#pragma unroll
            for (int i = 0; i < 4; i++) {
                int row = wm + (i >> 1) * 16 + g + (i & 1) * 8;
                statp[((size_t)b * HID + row) * 32 + blockIdx.x] =
                    make_float2(rmax[i], srow[row][0] + srow[row][1]);
            }
        }
    }
}

// ---------------------------------------------------------------------------
// Reduce the 32 per-chunk stats into {max, 1/sumexp} per q-row.
// ---------------------------------------------------------------------------
__global__ void __launch_bounds__(256) stats_reduce()
{
    int row  = blockIdx.x * 8 + (threadIdx.x >> 5);   // 0..2047
    int lane = threadIdx.x & 31;

    float2 p = g_statp[(size_t)row * 32 + lane];
    float M = p.x;
#pragma unroll
    for (int o = 16; o > 0; o >>= 1) M = fmaxf(M, __shfl_xor_sync(~0u, M, o));
    float s = p.y * __expf(p.x - M);
#pragma unroll
    for (int o = 16; o > 0; o >>= 1) s += __shfl_xor_sync(~0u, s, o);
    if (lane == 0) g_stats[row] = make_float2(M, 1.0f / s);
}

// ---------------------------------------------------------------------------
// gemm2: pure cp.async 3-stage pipeline on PRE-ROUNDED tf32 operands.
// ---------------------------------------------------------------------------
__global__ void __launch_bounds__(256)
gemm2_async(const float* __restrict__ A, const float* __restrict__ B,
            float* __restrict__ C)
{
    extern __shared__ uint32_t sm[];
    const int K = HID;                  // 128

    int b = blockIdx.z;
    const float* Ab = A + (size_t)b * (CDIM * HID) + (size_t)(blockIdx.y * 128) * K;
    const float* Bb = B + (size_t)b * (256 * NPIX) + blockIdx.x * 128;
    float*       Cb = C + (size_t)b * (CDIM * NPIX) + (size_t)(blockIdx.y * 128) * NPIX
                        + blockIdx.x * 128;

    int tid  = threadIdx.x;
    int lane = tid & 31, warp = tid >> 5;
    int g = lane >> 2, t = lane & 3;
    int wm = (warp >> 1) * 32;
    int wn = (warp & 1) * 64;

    uint32_t smb = (uint32_t)__cvta_generic_to_shared(sm);
    int nsteps = K >> 4;                // 8

    GX_ISSUE(0, nsteps, K);
    GX_ISSUE(1, nsteps, K);

    float acc[2][8][4] = {};

    for (int s = 0; s < nsteps; s++) {
        CP_WAIT1();
        __syncthreads();
        GX_ISSUE(s + 2, nsteps, K);

        const uint32_t* As = sm + (s % G2_NST) * G2_STG;
        const uint32_t* Bs = As + G2_ASZ;

#pragma unroll
        for (int k8 = 0; k8 < 16; k8 += 8) {
            uint32_t af[2][4], bf[8][2];
#pragma unroll
            for (int mt = 0; mt < 2; mt++) {
                int r = wm + mt * 16 + g;
                af[mt][0] = As[r * PAD + k8 + t];
                af[mt][1] = As[(r + 8) * PAD + k8 + t];
                af[mt][2] = As[r * PAD + k8 + t + 4];
                af[mt][3] = As[(r + 8) * PAD + k8 + t + 4];
            }
#pragma unroll
            for (int nt = 0; nt < 8; nt++) {
                int c = wn + nt * 8 + g;
                bf[nt][0] = Bs[(k8 + t) * BPITCH + c];
                bf[nt][1] = Bs[(k8 + t + 4) * BPITCH + c];
            }
#pragma unroll
            for (int mt = 0; mt < 2; mt++)
#pragma unroll
                for (int nt = 0; nt < 8; nt++)
                    mma_tf32(acc[mt][nt],
                             af[mt][0], af[mt][1], af[mt][2], af[mt][3],
                             bf[nt][0], bf[nt][1]);
        }
        __syncthreads();
    }

#pragma unroll
    for (int mt = 0; mt < 2; mt++) {
        int r0 = wm + mt * 16 + g;
#pragma unroll
        for (int nt = 0; nt < 8; nt++) {
            int c0 = wn + nt * 8 + 2 * t;
            float2 lo = {acc[mt][nt][0], acc[mt][nt][1]};
            float2 hi = {acc[mt][nt][2], acc[mt][nt][3]};
            *(float2*)&Cb[(size_t)r0       * NPIX + c0] = lo;
            *(float2*)&Cb[(size_t)(r0 + 8) * NPIX + c0] = hi;
        }
    }
}

// ---------------------------------------------------------------------------
// Fused: softmax-n applied on load (tf32-rounded copy written back for gemm2)
// + per-column softmax over d + partial context via tf32 MMA.
// ---------------------------------------------------------------------------
__global__ void __launch_bounds__(256) ctx_part_kernel()
{
    int bid = blockIdx.x;               // 0..511
    int p   = bid & (NGRP - 1);
    int bh  = bid >> 3;
    int b   = bh >> 2, h = bh & 3;

    float* qp_base = g_qkv + ((size_t)b * 256 + h * DHEAD) * NPIX;
    const float* vp_base = g_qkv + ((size_t)b * 256 + 128 + h * DHEAD) * NPIX;

    __shared__ float kst[DHEAD][CPITCH];
    __shared__ float vst[DHEAD][CPITCH];

    int tid = threadIdx.x;
    int lane = tid & 31, warp = tid >> 5;
    int g = lane >> 2, t = lane & 3;
    int mrow = (warp >> 2) * 16;
    int ncol = (warp & 3) * 8;

    float acc[4] = {};

    for (int c4 = 0; c4 < 4; c4++) {
        int n0 = (p * 4 + c4) * CHW;
        if (c4) __syncthreads();

#pragma unroll
        for (int r = 0; r < 4; r++) {
            int idx = tid + r * 256;
            int row = idx >> 5;         // d 0..31
            int col = (idx & 31) * 4;
            float2 st = g_stats[(b << 7) + (h << 5) + row];
            float4 qv = *(const float4*)&qp_base[(size_t)row * NPIX + n0 + col];
            float4 nq = normexp4(qv, st);
            *(float4*)&kst[row][col] = nq;
            uint4 rq = cvt4(nq);
            *(uint4*)&qp_base[(size_t)row * NPIX + n0 + col] = rq;
            *(float4*)&vst[row][col] = *(const float4*)&vp_base[(size_t)row * NPIX + n0 + col];
        }
        __syncthreads();

        if (tid < CHW) {
            float e[DHEAD];
            float m = -1e30f;
#pragma unroll
            for (int d = 0; d < DHEAD; d++) { e[d] = kst[d][tid]; m = fmaxf(m, e[d]); }
            float s = 0.f;
#pragma unroll
            for (int d = 0; d < DHEAD; d++) { e[d] = __expf(e[d] - m); s += e[d]; }
            float inv = 1.0f / s;
#pragma unroll
            for (int d = 0; d < DHEAD; d++) kst[d][tid] = e[d] * inv;
        }
        __syncthreads();

#pragma unroll
        for (int k8 = 0; k8 < CHW; k8 += 8) {
            uint32_t a0 = f2tf32(kst[mrow + g    ][k8 + t]);
            uint32_t a1 = f2tf32(kst[mrow + g + 8][k8 + t]);
            uint32_t a2 = f2tf32(kst[mrow + g    ][k8 + t + 4]);
            uint32_t a3 = f2tf32(kst[mrow + g + 8][k8 + t + 4]);
            uint32_t b0 = f2tf32(vst[ncol + g][k8 + t]);
            uint32_t b1 = f2tf32(vst[ncol + g][k8 + t + 4]);
            mma_tf32(acc, a0, a1, a2, a3, b0, b1);
        }
    }

    float* pp = g_ctxp + ((size_t)bh * NGRP + p) * 1024;
    float2 lo = {acc[0], acc[1]};
    float2 hi = {acc[2], acc[3]};
    *(float2*)&pp[(mrow + g    ) * DHEAD + ncol + 2 * t] = lo;
    *(float2*)&pp[(mrow + g + 8) * DHEAD + ncol + 2 * t] = hi;
}

// ---------------------------------------------------------------------------
// Merged: reduce ctx partials + compose W2 (tf32-rounded). One block per (b,h).
// ---------------------------------------------------------------------------
__global__ void __launch_bounds__(256) ctxw2_kernel(const float* __restrict__ w_out)
{
    int bh = blockIdx.x;                // b*4 + h
    int b  = bh >> 2, h = bh & 3;

    __shared__ float ctx[1024];         // [k][v] 32x32
    __shared__ float ws[256][33];       // w_out[:, h*32 : h*32+32]
    int tid = threadIdx.x;
    const float* base = g_ctxp + (size_t)bh * (NGRP * 1024);

#pragma unroll
    for (int j = 0; j < 4; j++) {
        int e = tid + j * 256;
        float s = 0.f;
#pragma unroll
        for (int p = 0; p < NGRP; p++) s += base[p * 1024 + e];
        ctx[e] = s;
    }
#pragma unroll
    for (int j = 0; j < 32; j++) {
        int i = tid + j * 256;
        int o = i >> 5, v = i & 31;
        ws[o][v] = w_out[o * HID + h * DHEAD + v];
    }
    __syncthreads();

    int o = tid;
    float wrow[32];
#pragma unroll
    for (int v = 0; v < 32; v++) wrow[v] = ws[o][v];

    float* w2p = g_W2 + ((size_t)b * CDIM + o) * HID + h * DHEAD;
#pragma unroll
    for (int kk = 0; kk < 32; kk++) {
        float s = 0.f;
#pragma unroll
        for (int v = 0; v < 32; v++) s = fmaf(wrow[v], ctx[kk * 32 + v], s);
        w2p[kk] = __uint_as_float(f2tf32(s));
    }
}

// ---------------------------------------------------------------------------
extern "C" void kernel_launch(void* const* d_in, const int* in_sizes, int n_in,
                              void* d_out, int out_size)
{
    const float* x     = (const float*)d_in[0];
    const float* w_qkv = (const float*)d_in[1];
    const float* w_out = (const float*)d_in[2];
    float*       out   = (float*)d_out;

    float  *qkv_p, *w2_p;
    float2 *stp_p;
    cudaGetSymbolAddress((void**)&qkv_p, g_qkv);
    cudaGetSymbolAddress((void**)&w2_p,  g_W2);
    cudaGetSymbolAddress((void**)&stp_p, g_statp);

    cudaFuncSetAttribute(gemm1_async, cudaFuncAttributeMaxDynamicSharedMemorySize, G2_SMEM);
    cudaFuncSetAttribute(gemm2_async, cudaFuncAttributeMaxDynamicSharedMemorySize, G2_SMEM);

    dim3 gg(NPIX / 128, 2, BATCH);

    // 1) q and v projections (cp.async) + fused softmax-n partial stats
    //    blockIdx.y=0 -> w_qkv rows 0-127 (q), y=1 -> rows 256-383 (v)
    gemm1_async<<<gg, 256, G2_SMEM>>>(w_qkv, x, qkv_p, stp_p, 256);
    // 2) tiny stats reduce
    stats_reduce<<<BATCH * HID / 8, 256>>>();
    // 3) fused softmax-n (tf32-rounded writeback) + softmax-d + partial ctx
    ctx_part_kernel<<<BATCH * NHEADS * NGRP, 256>>>();
    // 4) merged reduce + W2 compose
    ctxw2_kernel<<<BATCH * NHEADS, 256>>>(w_out);
    // 5) y = W2 @ normexp(q): cp.async GEMM on pre-rounded operands
    gemm2_async<<<gg, 256, G2_SMEM>>>(w2_p, qkv_p, out);
}